// round 3
// baseline (speedup 1.0000x reference)
#include <cuda_runtime.h>

#define N_NODES 100000
#define N_EDGES 3200000
#define N_GRAPHS 1000
#define IN_DIM 10
#define HID 20
#define CAP 96
#define BN_EPS 1e-5f

#define TB 256
#define NBLK_N ((N_NODES + TB - 1) / TB)   // 391 blocks for node-parallel kernels

// ---- device scratch (static globals; no runtime allocation) ----
__device__ int    g_cur[N_NODES];                    // degree / fill cursor
__device__ int    g_src[CAP * N_NODES];              // transposed neighbor lists: g_src[k*N + i]
__device__ __align__(16) float g_h[N_NODES * HID];   // normalized activations (layer input)
__device__ __align__(16) float g_tmp[N_NODES * HID]; // pre-BN activations
__device__ float  g_bsum[NBLK_N * HID];              // per-block BN partial sums
__device__ float  g_bsq[NBLK_N * HID];               // per-block BN partial sum-squares
__device__ float  g_ab[2 * HID];                     // folded BN: y*a + b
__device__ float  g_pool[N_GRAPHS * HID];

__global__ void k_zero_cur() {
    int i = blockIdx.x * blockDim.x + threadIdx.x;
    if (i < N_NODES) g_cur[i] = 0;
}

__global__ void k_fill(const int* __restrict__ ei) {
    int e = blockIdx.x * blockDim.x + threadIdx.x;
    if (e >= N_EDGES) return;
    int s = ei[e];
    int d = ei[N_EDGES + e];
    // defensive clamp: if dtype assumption is ever wrong we get wrong answers,
    // not an illegal-address crash
    s = min(max(s, 0), N_NODES - 1);
    d = min(max(d, 0), N_NODES - 1);
    int p = atomicAdd(&g_cur[d], 1);
    if (p < CAP) g_src[p * N_NODES + d] = s;
}

__global__ void k_zero_pool() {
    int i = blockIdx.x * blockDim.x + threadIdx.x;
    for (int j = i; j < N_GRAPHS * HID; j += blockDim.x * gridDim.x) g_pool[j] = 0.f;
}

// Gather + (h+agg)@W + b, write pre-BN to g_tmp, write per-block BN partials.
template <int DIN>
__global__ void k_gin(const float* __restrict__ xin,
                      const float* __restrict__ W,
                      const float* __restrict__ bias) {
    __shared__ float sW[DIN * HID];
    __shared__ float sb[HID];
    __shared__ float sws[8][HID];
    __shared__ float swq[8][HID];

    const float* hin = (DIN == IN_DIM) ? xin : (const float*)g_h;

    int t = threadIdx.x;
    for (int j = t; j < DIN * HID; j += blockDim.x) sW[j] = W[j];
    if (t < HID) sb[t] = bias[t];
    __syncthreads();

    int i = blockIdx.x * blockDim.x + t;
    float y[HID];
#pragma unroll
    for (int j = 0; j < HID; j++) y[j] = 0.f;

    if (i < N_NODES) {
        float acc[DIN];
        // own row ((1+eps)*x_i with eps=0)
        if (DIN == 20) {
            const float4* hp = (const float4*)(hin + (size_t)i * DIN);
#pragma unroll
            for (int d = 0; d < 5; d++) {
                float4 v = hp[d];
                acc[4*d] = v.x; acc[4*d+1] = v.y; acc[4*d+2] = v.z; acc[4*d+3] = v.w;
            }
        } else {
            const float2* hp = (const float2*)(hin + (size_t)i * DIN);
#pragma unroll
            for (int d = 0; d < 5; d++) {
                float2 v = hp[d];
                acc[2*d] = v.x; acc[2*d+1] = v.y;
            }
        }
        int deg = min(g_cur[i], CAP);
#pragma unroll 2
        for (int k = 0; k < deg; k++) {
            int s = g_src[k * N_NODES + i];
            if (DIN == 20) {
                const float4* hp = (const float4*)(hin + (size_t)s * DIN);
#pragma unroll
                for (int d = 0; d < 5; d++) {
                    float4 v = hp[d];
                    acc[4*d] += v.x; acc[4*d+1] += v.y; acc[4*d+2] += v.z; acc[4*d+3] += v.w;
                }
            } else {
                const float2* hp = (const float2*)(hin + (size_t)s * DIN);
#pragma unroll
                for (int d = 0; d < 5; d++) {
                    float2 v = hp[d];
                    acc[2*d] += v.x; acc[2*d+1] += v.y;
                }
            }
        }
        // tiny GEMV: y = acc @ W + b
#pragma unroll
        for (int j = 0; j < HID; j++) {
            float v = sb[j];
#pragma unroll
            for (int d = 0; d < DIN; d++) v += acc[d] * sW[d * HID + j];
            y[j] = v;
        }
        float4* tp = (float4*)(g_tmp + (size_t)i * HID);
#pragma unroll
        for (int j = 0; j < 5; j++)
            tp[j] = make_float4(y[4*j], y[4*j+1], y[4*j+2], y[4*j+3]);
    }

    // BN stats: warp shfl-reduce -> shared -> per-block partials to global (float)
    int lane = t & 31, wid = t >> 5;
#pragma unroll
    for (int j = 0; j < HID; j++) {
        float s = y[j], q = y[j] * y[j];
#pragma unroll
        for (int o = 16; o; o >>= 1) {
            s += __shfl_down_sync(0xffffffff, s, o);
            q += __shfl_down_sync(0xffffffff, q, o);
        }
        if (lane == 0) { sws[wid][j] = s; swq[wid][j] = q; }
    }
    __syncthreads();
    if (t < HID) {
        float s = 0.f, q = 0.f;
#pragma unroll
        for (int w = 0; w < 8; w++) { s += sws[w][t]; q += swq[w][t]; }
        g_bsum[blockIdx.x * HID + t] = s;
        g_bsq[blockIdx.x * HID + t]  = q;
    }
}

// Reduce per-block partials (double accumulation in registers), fold BN affine.
__global__ void k_finalize(const float* __restrict__ g, const float* __restrict__ beta) {
    int j = threadIdx.x;
    if (j < HID) {
        double s = 0.0, q = 0.0;
        for (int b = 0; b < NBLK_N; b++) {
            s += (double)g_bsum[b * HID + j];
            q += (double)g_bsq[b * HID + j];
        }
        float mu  = (float)(s / (double)N_NODES);
        float var = (float)(q / (double)N_NODES) - mu * mu;
        float a = rsqrtf(var + BN_EPS) * g[j];
        g_ab[j] = a;
        g_ab[HID + j] = beta[j] - mu * a;
    }
}

__global__ void k_norm() {
    int idx = blockIdx.x * blockDim.x + threadIdx.x;
    if (idx < N_NODES * HID) {
        int j = idx % HID;
        float v = g_tmp[idx] * g_ab[j] + g_ab[HID + j];
        g_h[idx] = fmaxf(v, 0.f);
    }
}

// layer-3 normalize fused with global add-pool (float atomics)
__global__ void k_norm_pool(const int* __restrict__ batch) {
    int i = blockIdx.x * blockDim.x + threadIdx.x;
    if (i >= N_NODES) return;
    int gi = batch[i];
    gi = min(max(gi, 0), N_GRAPHS - 1);
    float* pool = g_pool + gi * HID;
#pragma unroll
    for (int j = 0; j < HID; j++) {
        float v = fmaxf(g_tmp[(size_t)i * HID + j] * g_ab[j] + g_ab[HID + j], 0.f);
        atomicAdd(&pool[j], v);
    }
}

__global__ void k_fc(const float* __restrict__ fcW, const float* __restrict__ fcb,
                     float* __restrict__ out) {
    int g = blockIdx.x * blockDim.x + threadIdx.x;
    if (g < N_GRAPHS) {
        float o0 = fcb[0], o1 = fcb[1];
#pragma unroll
        for (int j = 0; j < HID; j++) {
            float p = g_pool[g * HID + j];
            o0 += p * fcW[j * 2 + 0];
            o1 += p * fcW[j * 2 + 1];
        }
        out[g * 2 + 0] = o0;
        out[g * 2 + 1] = o1;
    }
}

extern "C" void kernel_launch(void* const* d_in, const int* in_sizes, int n_in,
                              void* d_out, int out_size) {
    const float* x     = (const float*)d_in[0];
    const int*   ei    = (const int*)d_in[1];     // int32 (JAX x64 disabled)
    const int*   batch = (const int*)d_in[2];     // int32
    const float* W1  = (const float*)d_in[3];
    const float* b1  = (const float*)d_in[4];
    const float* g1  = (const float*)d_in[5];
    const float* be1 = (const float*)d_in[6];
    const float* W2  = (const float*)d_in[7];
    const float* b2  = (const float*)d_in[8];
    const float* g2  = (const float*)d_in[9];
    const float* be2 = (const float*)d_in[10];
    const float* W3  = (const float*)d_in[11];
    const float* b3  = (const float*)d_in[12];
    const float* g3  = (const float*)d_in[13];
    const float* be3 = (const float*)d_in[14];
    const float* fcW = (const float*)d_in[15];
    const float* fcb = (const float*)d_in[16];
    float* out = (float*)d_out;

    const int NB_E  = (N_EDGES + TB - 1) / TB;
    const int NB_NH = (N_NODES * HID + TB - 1) / TB;

    // build reverse adjacency (fixed-capacity transposed slots)
    k_zero_cur<<<NBLK_N, TB>>>();
    k_fill<<<NB_E, TB>>>(ei);
    k_zero_pool<<<40, TB>>>();

    // layer 1 (DIN=10, reads x)
    k_gin<IN_DIM><<<NBLK_N, TB>>>(x, W1, b1);
    k_finalize<<<1, 32>>>(g1, be1);
    k_norm<<<NB_NH, TB>>>();

    // layer 2
    k_gin<HID><<<NBLK_N, TB>>>(nullptr, W2, b2);
    k_finalize<<<1, 32>>>(g2, be2);
    k_norm<<<NB_NH, TB>>>();

    // layer 3 (normalize fused with pooling)
    k_gin<HID><<<NBLK_N, TB>>>(nullptr, W3, b3);
    k_finalize<<<1, 32>>>(g3, be3);
    k_norm_pool<<<NBLK_N, TB>>>(batch);

    // readout
    k_fc<<<(N_GRAPHS + TB - 1) / TB, TB>>>(fcW, fcb, out);
}

// round 4
// speedup vs baseline: 1.8509x; 1.8509x over previous
#include <cuda_runtime.h>
#include <cuda_fp16.h>

#define N_NODES 100000
#define N_EDGES 3200000
#define N_GRAPHS 1000
#define IN_DIM 10
#define HID 20
#define CAP 96
#define BN_EPS 1e-5f

#define TB 256
#define NBLK_N ((N_NODES + TB - 1) / TB)   // 391

// ---- device scratch ----
__device__ int    g_cur[N_NODES];
__device__ int    g_src[CAP * N_NODES];              // transposed: g_src[k*N + i]
__device__ __align__(16) __half g_xh[N_NODES * 16];  // x in half, padded 10->16
__device__ __align__(16) __half g_hh[N_NODES * 24];  // h in half, padded 20->24
__device__ __align__(16) float  g_tmp[N_NODES * HID];// pre-BN activations (fp32)
__device__ float  g_bsum[NBLK_N * HID];
__device__ float  g_bsq[NBLK_N * HID];
__device__ float  g_ab[2 * HID];                     // folded BN: y*a + b

__global__ void k_zero_cur() {
    int i = blockIdx.x * blockDim.x + threadIdx.x;
    if (i < N_NODES) g_cur[i] = 0;
}

__global__ void k_fill(const int* __restrict__ ei) {
    int e = blockIdx.x * blockDim.x + threadIdx.x;
    if (e >= N_EDGES) return;
    int s = ei[e];
    int d = ei[N_EDGES + e];
    s = min(max(s, 0), N_NODES - 1);
    d = min(max(d, 0), N_NODES - 1);
    int p = atomicAdd(&g_cur[d], 1);
    if (p < CAP) g_src[p * N_NODES + d] = s;
}

// convert x (fp32, 10 dims) -> half rows padded to 16
__global__ void k_x2h(const float* __restrict__ x) {
    int i = blockIdx.x * blockDim.x + threadIdx.x;
    if (i >= N_NODES) return;
    const float2* xp = (const float2*)(x + (size_t)i * IN_DIM);
    __half2 h[8];
#pragma unroll
    for (int q = 0; q < 5; q++) { float2 v = xp[q]; h[q] = __floats2half2_rn(v.x, v.y); }
#pragma unroll
    for (int q = 5; q < 8; q++) h[q] = __floats2half2_rn(0.f, 0.f);
    int4* op = (int4*)(g_xh + (size_t)i * 16);
    op[0] = *(int4*)&h[0];
    op[1] = *(int4*)&h[4];
}

template <int DR, int DP>
__device__ __forceinline__ void add_row(float* acc, const __half* __restrict__ hin, int s) {
    const int4* hp = (const int4*)(hin + (size_t)s * DP);
#pragma unroll
    for (int q = 0; q < DP / 8; q++) {
        int4 v = hp[q];
        int w[4] = {v.x, v.y, v.z, v.w};
#pragma unroll
        for (int c = 0; c < 4; c++) {
            int base = q * 8 + c * 2;
            if (base < DR) {
                float2 f = __half22float2(*(__half2*)&w[c]);
                acc[base] += f.x;
                if (base + 1 < DR) acc[base + 1] += f.y;
            }
        }
    }
}

// Gather(half) + (h+agg)@W + b -> g_tmp(fp32), per-block BN partials.
template <int DR, int DP>
__global__ void k_gin(const float* __restrict__ W, const float* __restrict__ bias) {
    __shared__ float sW[DR * HID];
    __shared__ float sb[HID];
    __shared__ float sws[8][HID];
    __shared__ float swq[8][HID];

    const __half* hin = (DR == IN_DIM) ? (const __half*)g_xh : (const __half*)g_hh;

    int t = threadIdx.x;
    for (int j = t; j < DR * HID; j += blockDim.x) sW[j] = W[j];
    if (t < HID) sb[t] = bias[t];
    __syncthreads();

    int i = blockIdx.x * blockDim.x + t;
    float y[HID];
#pragma unroll
    for (int j = 0; j < HID; j++) y[j] = 0.f;

    if (i < N_NODES) {
        float acc[DR];
#pragma unroll
        for (int d = 0; d < DR; d++) acc[d] = 0.f;
        add_row<DR, DP>(acc, hin, i);          // own row (eps = 0)

        int deg = min(g_cur[i], CAP);
        const int* sp = g_src + i;
        int k = 0;
        for (; k + 4 <= deg; k += 4) {
            int s0 = sp[(k + 0) * N_NODES];
            int s1 = sp[(k + 1) * N_NODES];
            int s2 = sp[(k + 2) * N_NODES];
            int s3 = sp[(k + 3) * N_NODES];
            add_row<DR, DP>(acc, hin, s0);
            add_row<DR, DP>(acc, hin, s1);
            add_row<DR, DP>(acc, hin, s2);
            add_row<DR, DP>(acc, hin, s3);
        }
        for (; k < deg; k++) add_row<DR, DP>(acc, hin, sp[k * N_NODES]);

        // tiny GEMV
#pragma unroll
        for (int j = 0; j < HID; j++) {
            float v = sb[j];
#pragma unroll
            for (int d = 0; d < DR; d++) v += acc[d] * sW[d * HID + j];
            y[j] = v;
        }
        float4* tp = (float4*)(g_tmp + (size_t)i * HID);
#pragma unroll
        for (int j = 0; j < 5; j++)
            tp[j] = make_float4(y[4*j], y[4*j+1], y[4*j+2], y[4*j+3]);
    }

    // BN stats: warp shfl -> shared -> per-block float partials
    int lane = t & 31, wid = t >> 5;
#pragma unroll
    for (int j = 0; j < HID; j++) {
        float s = y[j], q = y[j] * y[j];
#pragma unroll
        for (int o = 16; o; o >>= 1) {
            s += __shfl_down_sync(0xffffffff, s, o);
            q += __shfl_down_sync(0xffffffff, q, o);
        }
        if (lane == 0) { sws[wid][j] = s; swq[wid][j] = q; }
    }
    __syncthreads();
    if (t < HID) {
        float s = 0.f, q = 0.f;
#pragma unroll
        for (int w = 0; w < 8; w++) { s += sws[w][t]; q += swq[w][t]; }
        g_bsum[blockIdx.x * HID + t] = s;
        g_bsq[blockIdx.x * HID + t]  = q;
    }
}

// parallel partial reduce: warp w handles channel w
__global__ void k_finalize(const float* __restrict__ g, const float* __restrict__ beta) {
    int w = threadIdx.x >> 5, lane = threadIdx.x & 31;
    if (w >= HID) return;
    double s = 0.0, q = 0.0;
    for (int b = lane; b < NBLK_N; b += 32) {
        s += (double)g_bsum[b * HID + w];
        q += (double)g_bsq[b * HID + w];
    }
#pragma unroll
    for (int o = 16; o; o >>= 1) {
        s += __shfl_down_sync(0xffffffff, s, o);
        q += __shfl_down_sync(0xffffffff, q, o);
    }
    if (lane == 0) {
        float mu  = (float)(s / (double)N_NODES);
        float var = (float)(q / (double)N_NODES) - mu * mu;
        float a = rsqrtf(var + BN_EPS) * g[w];
        g_ab[w] = a;
        g_ab[HID + w] = beta[w] - mu * a;
    }
}

// normalize + relu + convert to half padded rows (24)
__global__ void k_norm() {
    int i = blockIdx.x * blockDim.x + threadIdx.x;
    if (i >= N_NODES) return;
    const float4* tp = (const float4*)(g_tmp + (size_t)i * HID);
    __half2 h[12];
#pragma unroll
    for (int q = 0; q < 5; q++) {
        float4 v = tp[q];
        int j = 4 * q;
        float r0 = fmaxf(v.x * g_ab[j+0] + g_ab[HID+j+0], 0.f);
        float r1 = fmaxf(v.y * g_ab[j+1] + g_ab[HID+j+1], 0.f);
        float r2 = fmaxf(v.z * g_ab[j+2] + g_ab[HID+j+2], 0.f);
        float r3 = fmaxf(v.w * g_ab[j+3] + g_ab[HID+j+3], 0.f);
        h[2*q]   = __floats2half2_rn(r0, r1);
        h[2*q+1] = __floats2half2_rn(r2, r3);
    }
    h[10] = __floats2half2_rn(0.f, 0.f);
    h[11] = __floats2half2_rn(0.f, 0.f);
    int4* op = (int4*)(g_hh + (size_t)i * 24);
    op[0] = *(int4*)&h[0];
    op[1] = *(int4*)&h[4];
    op[2] = *(int4*)&h[8];
}

// warp per graph: binary-search node range (batch sorted), norm+relu+pool+fc
__global__ void k_pool_fc(const int* __restrict__ batch,
                          const float* __restrict__ fcW, const float* __restrict__ fcb,
                          float* __restrict__ out) {
    int gid = (blockIdx.x * blockDim.x + threadIdx.x) >> 5;
    int lane = threadIdx.x & 31;
    if (gid >= N_GRAPHS) return;

    int lo = 0, hi = N_NODES;
    while (lo < hi) { int mid = (lo + hi) >> 1; if (batch[mid] < gid) lo = mid + 1; else hi = mid; }
    int r0 = lo;
    hi = N_NODES;
    while (lo < hi) { int mid = (lo + hi) >> 1; if (batch[mid] < gid + 1) lo = mid + 1; else hi = mid; }
    int r1 = lo;

    float a = 0.f, b = 0.f, w0 = 0.f, w1 = 0.f;
    if (lane < HID) {
        a = g_ab[lane]; b = g_ab[HID + lane];
        w0 = fcW[lane * 2 + 0]; w1 = fcW[lane * 2 + 1];
    }
    float pool = 0.f;
    for (int n = r0; n < r1; n++) {
        float v = (lane < HID) ? g_tmp[(size_t)n * HID + lane] * a + b : 0.f;
        pool += fmaxf(v, 0.f);
    }
    float o0 = pool * w0, o1 = pool * w1;
#pragma unroll
    for (int o = 16; o; o >>= 1) {
        o0 += __shfl_down_sync(0xffffffff, o0, o);
        o1 += __shfl_down_sync(0xffffffff, o1, o);
    }
    if (lane == 0) {
        out[gid * 2 + 0] = o0 + fcb[0];
        out[gid * 2 + 1] = o1 + fcb[1];
    }
}

extern "C" void kernel_launch(void* const* d_in, const int* in_sizes, int n_in,
                              void* d_out, int out_size) {
    const float* x     = (const float*)d_in[0];
    const int*   ei    = (const int*)d_in[1];
    const int*   batch = (const int*)d_in[2];
    const float* W1  = (const float*)d_in[3];
    const float* b1  = (const float*)d_in[4];
    const float* g1  = (const float*)d_in[5];
    const float* be1 = (const float*)d_in[6];
    const float* W2  = (const float*)d_in[7];
    const float* b2  = (const float*)d_in[8];
    const float* g2  = (const float*)d_in[9];
    const float* be2 = (const float*)d_in[10];
    const float* W3  = (const float*)d_in[11];
    const float* b3  = (const float*)d_in[12];
    const float* g3  = (const float*)d_in[13];
    const float* be3 = (const float*)d_in[14];
    const float* fcW = (const float*)d_in[15];
    const float* fcb = (const float*)d_in[16];
    float* out = (float*)d_out;

    const int NB_E = (N_EDGES + TB - 1) / TB;

    k_zero_cur<<<NBLK_N, TB>>>();
    k_fill<<<NB_E, TB>>>(ei);
    k_x2h<<<NBLK_N, TB>>>(x);

    // layer 1
    k_gin<IN_DIM, 16><<<NBLK_N, TB>>>(W1, b1);
    k_finalize<<<1, 640>>>(g1, be1);
    k_norm<<<NBLK_N, TB>>>();

    // layer 2
    k_gin<HID, 24><<<NBLK_N, TB>>>(W2, b2);
    k_finalize<<<1, 640>>>(g2, be2);
    k_norm<<<NBLK_N, TB>>>();

    // layer 3
    k_gin<HID, 24><<<NBLK_N, TB>>>(W3, b3);
    k_finalize<<<1, 640>>>(g3, be3);

    // norm + pool + fc fused (batch sorted -> contiguous ranges)
    k_pool_fc<<<(N_GRAPHS * 32 + TB - 1) / TB, TB>>>(batch, fcW, fcb, out);
}